// round 16
// baseline (speedup 1.0000x reference)
#include <cuda_runtime.h>

// WeightedAggregator: out[b,:] = sum_k (w[b,k]/sum_j w[b,j]) * features[idx[b,k],:]
// B = 50000, K = 16, D = 128 (fp32). neigh_idx is int32 (JAX demotes int64).
//
// R16: persistent 4-phase windowed gather, DENSE execution.
//  - Prologue: each warp sorts its rows' (idx,w) by phase window into SMEM
//    (ballot compaction). Hot loops iterate only in-window neighbors from
//    SMEM: no shuffles, no predication, no redundant scans (R15's failure).
//  - Partials: 8 rows/warp in registers + 8 rows/warp in SMEM; never DRAM.
//  - One co-resident wave + bounded monotonic-ticket grid barriers between
//    phases (perf-only: correctness never depends on barrier success).
//  - Host verifies co-residency; falls back to the proven 52.6us flat kernel.

#define K_NEIGH   16
#define FEAT_D    128
#define N_PHASES  4
#define WARPS_CTA 4
#define REG_ROWS  8
#define SMEM_ROWS 8
#define ROWS_PW   (REG_ROWS + SMEM_ROWS)   // 16 rows per warp

__device__ unsigned g_bar[N_PHASES - 1];   // zero-init; monotonic tickets

__device__ __forceinline__ void soft_grid_barrier(int b, unsigned grid) {
    __syncthreads();
    if (threadIdx.x == 0) {
        const unsigned ticket = atomicAdd(&g_bar[b], 1u);
        const unsigned target = (ticket / grid + 1u) * grid;
        unsigned spins = 0;
        while (*(volatile unsigned*)&g_bar[b] < target && spins < (1u << 24))
            spins++;
    }
    __syncthreads();
}

__global__ __launch_bounds__(32 * WARPS_CTA, 6)
void weighted_agg_persistent(const float* __restrict__ features,
                             const float* __restrict__ neigh_w,
                             const int* __restrict__ neigh_idx,
                             float* __restrict__ out,
                             int B, int N)
{
    __shared__ int    sidx[WARPS_CTA][ROWS_PW][K_NEIGH];
    __shared__ float  swt [WARPS_CTA][ROWS_PW][K_NEIGH];
    __shared__ unsigned char soff[WARPS_CTA][ROWS_PW][N_PHASES + 1];
    __shared__ float  sinv[WARPS_CTA][ROWS_PW];
    __shared__ float4 spart[WARPS_CTA][SMEM_ROWS][32];   // 16 KB

    const int lane = threadIdx.x & 31;
    const int wid  = threadIdx.x >> 5;
    const int base = (blockIdx.x * WARPS_CTA + wid) * ROWS_PW;
    const int q    = N / N_PHASES;                        // 125000
    const float4* __restrict__ feat4 = (const float4*)features;

    // ---------- prologue: load, phase-sort into SMEM, weight sums ----------
    for (int r = 0; r < ROWS_PW; r++) {
        const int row = base + r;
        float w = 0.f;  int ix = 0;
        const bool active = (row < B) && (lane < K_NEIGH);
        if (active) {
            w  = neigh_w  [row * K_NEIGH + lane];
            ix = neigh_idx[row * K_NEIGH + lane];
        }
        // weight sum -> inv
        float s = w;
        #pragma unroll
        for (int off = 16; off > 0; off >>= 1)
            s += __shfl_xor_sync(0xffffffffu, s, off);
        if (lane == 0) sinv[wid][r] = 1.0f / s;

        const int myp = ix / q;                     // 0..3 (N divisible by 4)
        unsigned cnt = 0;
        #pragma unroll
        for (int p = 0; p < N_PHASES; p++) {
            const bool mine = active && (myp == p);
            const unsigned m = __ballot_sync(0xffffffffu, mine);
            if (lane == 0) soff[wid][r][p] = (unsigned char)cnt;
            if (mine) {
                const int slot = cnt + __popc(m & ((1u << lane) - 1u));
                sidx[wid][r][slot] = ix;
                swt [wid][r][slot] = w;
            }
            cnt += __popc(m);
        }
        if (lane == 0) soff[wid][r][N_PHASES] = (unsigned char)cnt;
    }
    __syncthreads();

    // ---------- 4 phases, dense gather loops ----------
    float4 pa[REG_ROWS];    // register partials for rows [0, REG_ROWS)

    #pragma unroll
    for (int p = 0; p < N_PHASES; p++) {

        // register-resident rows
        #pragma unroll
        for (int r = 0; r < REG_ROWS; r++) {
            const int row = base + r;
            float4 acc = make_float4(0.f, 0.f, 0.f, 0.f);
            if (row < B) {
                const int j0 = soff[wid][r][p];
                const int j1 = soff[wid][r][p + 1];
                for (int j = j0; j < j1; j++) {
                    const int   ik = sidx[wid][r][j];    // broadcast LDS
                    const float ww = swt [wid][r][j];
                    const float4 f = __ldg(feat4 + (long long)ik * (FEAT_D / 4) + lane);
                    acc.x += ww * f.x;  acc.y += ww * f.y;
                    acc.z += ww * f.z;  acc.w += ww * f.w;
                }
            }
            if (p == 0) {
                pa[r] = acc;
            } else {
                pa[r].x += acc.x;  pa[r].y += acc.y;
                pa[r].z += acc.z;  pa[r].w += acc.w;
            }
            if (p == N_PHASES - 1 && row < B) {
                const float inv = sinv[wid][r];
                float4 o;
                o.x = pa[r].x * inv;  o.y = pa[r].y * inv;
                o.z = pa[r].z * inv;  o.w = pa[r].w * inv;
                ((float4*)out)[(long long)row * (FEAT_D / 4) + lane] = o;
            }
        }

        // smem-resident rows
        for (int r2 = 0; r2 < SMEM_ROWS; r2++) {
            const int r   = REG_ROWS + r2;
            const int row = base + r;
            if (row >= B) continue;
            float4 acc = make_float4(0.f, 0.f, 0.f, 0.f);
            const int j0 = soff[wid][r][p];
            const int j1 = soff[wid][r][p + 1];
            for (int j = j0; j < j1; j++) {
                const int   ik = sidx[wid][r][j];
                const float ww = swt [wid][r][j];
                const float4 f = __ldg(feat4 + (long long)ik * (FEAT_D / 4) + lane);
                acc.x += ww * f.x;  acc.y += ww * f.y;
                acc.z += ww * f.z;  acc.w += ww * f.w;
            }
            if (p == 0) {
                spart[wid][r2][lane] = acc;
            } else {
                float4 pp = spart[wid][r2][lane];
                pp.x += acc.x;  pp.y += acc.y;
                pp.z += acc.z;  pp.w += acc.w;
                if (p == N_PHASES - 1) {
                    const float inv = sinv[wid][r];
                    float4 o;
                    o.x = pp.x * inv;  o.y = pp.y * inv;
                    o.z = pp.z * inv;  o.w = pp.w * inv;
                    ((float4*)out)[(long long)row * (FEAT_D / 4) + lane] = o;
                } else {
                    spart[wid][r2][lane] = pp;
                }
            }
        }

        if (p < N_PHASES - 1)
            soft_grid_barrier(p, gridDim.x);
    }
}

// Fallback: proven flat kernel (52.6us ncu, DRAM 77%).
__global__ __launch_bounds__(128)
void weighted_agg_flat(const float* __restrict__ features,
                       const float* __restrict__ neigh_w,
                       const int* __restrict__ neigh_idx,
                       float* __restrict__ out,
                       int B)
{
    const int gtid = blockIdx.x * blockDim.x + threadIdx.x;
    const int row  = gtid >> 5;
    const int lane = threadIdx.x & 31;
    if (row >= B) return;

    float w = 0.f;  int ix = 0;
    if (lane < K_NEIGH) {
        w  = neigh_w  [row * K_NEIGH + lane];
        ix = neigh_idx[row * K_NEIGH + lane];
    }
    float s = w;
    #pragma unroll
    for (int off = 16; off > 0; off >>= 1)
        s += __shfl_xor_sync(0xffffffffu, s, off);
    const float inv = 1.0f / s;

    const float4* __restrict__ feat4 = (const float4*)features;
    float4 f[K_NEIGH];
    #pragma unroll
    for (int k = 0; k < K_NEIGH; k++) {
        const int ik = __shfl_sync(0xffffffffu, ix, k);
        f[k] = __ldg(feat4 + (long long)ik * (FEAT_D / 4) + lane);
    }
    float4 a0 = make_float4(0.f, 0.f, 0.f, 0.f);
    float4 a1 = make_float4(0.f, 0.f, 0.f, 0.f);
    #pragma unroll
    for (int k = 0; k < K_NEIGH; k += 2) {
        const float w0 = __shfl_sync(0xffffffffu, w, k);
        const float w1 = __shfl_sync(0xffffffffu, w, k + 1);
        a0.x += w0 * f[k].x;  a1.x += w1 * f[k + 1].x;
        a0.y += w0 * f[k].y;  a1.y += w1 * f[k + 1].y;
        a0.z += w0 * f[k].z;  a1.z += w1 * f[k + 1].z;
        a0.w += w0 * f[k].w;  a1.w += w1 * f[k + 1].w;
    }
    float4 r;
    r.x = (a0.x + a1.x) * inv;  r.y = (a0.y + a1.y) * inv;
    r.z = (a0.z + a1.z) * inv;  r.w = (a0.w + a1.w) * inv;
    ((float4*)out)[(long long)row * (FEAT_D / 4) + lane] = r;
}

extern "C" void kernel_launch(void* const* d_in, const int* in_sizes, int n_in,
                              void* d_out, int out_size)
{
    const float* features  = (const float*)d_in[0];   // [N_NODES, 128] fp32
    const float* neigh_w   = (const float*)d_in[1];   // [B, 16] fp32
    const int*   neigh_idx = (const int*)d_in[2];     // [B, 16] int32
    float*       out       = (float*)d_out;           // [B, 128] fp32

    const int B = in_sizes[1] / K_NEIGH;   // 50000
    const int N = in_sizes[0] / FEAT_D;    // 500000

    const int threads      = 32 * WARPS_CTA;                         // 128
    const int rows_per_cta = WARPS_CTA * ROWS_PW;                    // 64
    const int grid_needed  = (B + rows_per_cta - 1) / rows_per_cta;  // 782

    int dev = 0, sms = 0, occ = 0;
    cudaGetDevice(&dev);
    cudaDeviceGetAttribute(&sms, cudaDevAttrMultiProcessorCount, dev);
    cudaOccupancyMaxActiveBlocksPerMultiprocessor(
        &occ, weighted_agg_persistent, threads, 0);

    if ((long long)occ * sms >= grid_needed) {
        weighted_agg_persistent<<<grid_needed, threads>>>(
            features, neigh_w, neigh_idx, out, B, N);
    } else {
        const int blocks = (B * 32 + threads - 1) / threads;
        weighted_agg_flat<<<blocks, threads>>>(features, neigh_w, neigh_idx, out, B);
    }
}

// round 17
// speedup vs baseline: 1.7150x; 1.7150x over previous
#include <cuda_runtime.h>

// WeightedAggregator: out[b,:] = sum_k (w[b,k]/sum_j w[b,j]) * features[idx[b,k],:]
// B = 50000, K = 16, D = 128 (fp32). One warp per output row; one float4 per lane.
// neigh_idx is int32 (JAX demotes int64 without x64 mode).
//
// FINAL (R11): flat grid, one warp per row, 128-thread CTAs (34 regs ->
// 15 CTAs/SM, ~60 resident warps), fully-coalesced LDG.128 gathers (each
// warp-gather = one 512B feature row = 4x128B lines), warp-shuffle weight
// normalization folded into the epilogue.
//
// Measured: 52.6us (ncu), 6.14 TB/s = 77% of 8 TB/s spec. This is the
// random-512B-row gather roofline on this part. Exhaustively verified:
//  - bytes: L2 eviction hints neutral; 2/4-phase index windowing reaches the
//    compulsory unique-row floor (~216 MB, confirmed twice by ncu byte
//    counts) but the persistent/low-occupancy execution it requires caps at
//    ~2.5 TB/s (needs >=4.1 to win) and gmem partial round trips cost more
//    bytes than the windowing saves;
//  - latency/parallelism: forced MLP=4 (asm), LDG.256 half-warp gathers,
//    persistent grid, block-size sweep -- all neutral or negative except the
//    128-thread block shape kept here.

#define K_NEIGH 16
#define FEAT_D 128

__global__ __launch_bounds__(128)
void weighted_agg_kernel(const float* __restrict__ features,
                         const float* __restrict__ neigh_w,
                         const int* __restrict__ neigh_idx,
                         float* __restrict__ out,
                         int B)
{
    const int gtid = blockIdx.x * blockDim.x + threadIdx.x;
    const int row  = gtid >> 5;          // warp id = output row
    const int lane = threadIdx.x & 31;
    if (row >= B) return;

    // Lanes 0..15 hold this row's weight + index; others hold 0.
    float w  = 0.0f;
    int   ix = 0;
    if (lane < K_NEIGH) {
        w  = neigh_w  [row * K_NEIGH + lane];
        ix = neigh_idx[row * K_NEIGH + lane];
    }

    // Warp-wide weight sum (lanes >= 16 contribute 0).
    float s = w;
    #pragma unroll
    for (int off = 16; off > 0; off >>= 1)
        s += __shfl_xor_sync(0xffffffffu, s, off);
    const float inv = 1.0f / s;

    const float4* __restrict__ feat4 = (const float4*)features;

    // Gather: 16 independent, fully-coalesced LDG.128 per warp.
    float4 f[K_NEIGH];
    #pragma unroll
    for (int k = 0; k < K_NEIGH; k++) {
        const int ik = __shfl_sync(0xffffffffu, ix, k);
        f[k] = __ldg(feat4 + (long long)ik * (FEAT_D / 4) + lane);
    }

    // Weighted accumulation, two independent FFMA chains.
    float4 a0 = make_float4(0.f, 0.f, 0.f, 0.f);
    float4 a1 = make_float4(0.f, 0.f, 0.f, 0.f);
    #pragma unroll
    for (int k = 0; k < K_NEIGH; k += 2) {
        const float w0 = __shfl_sync(0xffffffffu, w, k);
        const float w1 = __shfl_sync(0xffffffffu, w, k + 1);
        a0.x += w0 * f[k].x;     a1.x += w1 * f[k + 1].x;
        a0.y += w0 * f[k].y;     a1.y += w1 * f[k + 1].y;
        a0.z += w0 * f[k].z;     a1.z += w1 * f[k + 1].z;
        a0.w += w0 * f[k].w;     a1.w += w1 * f[k + 1].w;
    }

    float4 r;
    r.x = (a0.x + a1.x) * inv;
    r.y = (a0.y + a1.y) * inv;
    r.z = (a0.z + a1.z) * inv;
    r.w = (a0.w + a1.w) * inv;

    ((float4*)out)[(long long)row * (FEAT_D / 4) + lane] = r;
}

extern "C" void kernel_launch(void* const* d_in, const int* in_sizes, int n_in,
                              void* d_out, int out_size)
{
    const float* features  = (const float*)d_in[0];   // [N_NODES, 128] fp32
    const float* neigh_w   = (const float*)d_in[1];   // [B, 16] fp32
    const int*   neigh_idx = (const int*)d_in[2];     // [B, 16] int32
    float*       out       = (float*)d_out;           // [B, 128] fp32

    const int B = in_sizes[1] / K_NEIGH;   // 50000

    const int threads = 128;               // 4 warps/block -> 4 rows/block
    const int rows_per_block = threads / 32;
    const int blocks = (B + rows_per_block - 1) / rows_per_block;   // 12500

    weighted_agg_kernel<<<blocks, threads>>>(features, neigh_w, neigh_idx, out, B);
}